// round 1
// baseline (speedup 1.0000x reference)
#include <cuda_runtime.h>

// Problem constants
#define HH 256
#define WW 256
#define PP 512
#define NPIX (HH * WW)

// Scratch (device globals — no allocation allowed)
__device__ float g_sums[PP];   // per-point sum of wd^-5 over all pixels
__device__ float g_term1;      // sum of hm * min_dist
__device__ float g_sumabs;     // sum |hm|
__device__ float g_maxd;       // global max distance

__device__ __forceinline__ float fsqrt_approx(float x) {
    float y; asm("sqrt.approx.f32 %0, %1;" : "=f"(y) : "f"(x)); return y;
}
__device__ __forceinline__ float frcp_approx(float x) {
    float y; asm("rcp.approx.f32 %0, %1;" : "=f"(y) : "f"(x)); return y;
}

// ---------------------------------------------------------------------------
// K1: zero accumulators + compute global max distance.
// Distance to a fixed point is convex in grid coords, so the max over the
// lattice is attained at a corner grid point: max over P x 4 corners is exact.
// ---------------------------------------------------------------------------
__global__ void prep_kernel(const float* __restrict__ pts) {
    int p = threadIdx.x;  // 512 threads
    g_sums[p] = 0.0f;
    if (p == 0) { g_term1 = 0.0f; g_sumabs = 0.0f; }

    float py = pts[2 * p + 0];
    float px = pts[2 * p + 1];
    const float C = (float)(HH - 1);  // 255
    float d2 = 0.0f;
    {
        float a, b;
        a = 0.0f - py; b = 0.0f - px; d2 = fmaxf(d2, a * a + b * b);
        a = 0.0f - py; b = C    - px; d2 = fmaxf(d2, a * a + b * b);
        a = C    - py; b = 0.0f - px; d2 = fmaxf(d2, a * a + b * b);
        a = C    - py; b = C    - px; d2 = fmaxf(d2, a * a + b * b);
    }
    float dist = sqrtf(d2);

    __shared__ float sm[PP];
    sm[p] = dist;
    __syncthreads();
    for (int s = PP / 2; s > 0; s >>= 1) {
        if (p < s) sm[p] = fmaxf(sm[p], sm[p + s]);
        __syncthreads();
    }
    if (p == 0) g_maxd = sm[0];
}

// ---------------------------------------------------------------------------
// K2: term1 — per-pixel min distance over points (track min d^2, sqrt once),
// weighted by heatmap; also accumulate sum|hm|.
// One block per row; thread = column. Points cached in smem as (px, dy^2).
// ---------------------------------------------------------------------------
__global__ void term1_kernel(const float* __restrict__ heat,
                             const float* __restrict__ pts) {
    __shared__ float2 pc[PP];
    int h = blockIdx.x;
    int w = threadIdx.x;
    float fh = (float)h;

    for (int p = threadIdx.x; p < PP; p += blockDim.x) {
        float py = pts[2 * p + 0];
        float px = pts[2 * p + 1];
        float dy = fh - py;
        pc[p] = make_float2(px, dy * dy);
    }
    __syncthreads();

    float fw = (float)w;
    float m0 = 3.4e38f, m1 = 3.4e38f, m2 = 3.4e38f, m3 = 3.4e38f;
    #pragma unroll 4
    for (int p = 0; p < PP; p += 4) {
        float2 a0 = pc[p + 0], a1 = pc[p + 1], a2 = pc[p + 2], a3 = pc[p + 3];
        float t0 = fw - a0.x; m0 = fminf(m0, fmaf(t0, t0, a0.y));
        float t1 = fw - a1.x; m1 = fminf(m1, fmaf(t1, t1, a1.y));
        float t2 = fw - a2.x; m2 = fminf(m2, fmaf(t2, t2, a2.y));
        float t3 = fw - a3.x; m3 = fminf(m3, fmaf(t3, t3, a3.y));
    }
    float m = fminf(fminf(m0, m1), fminf(m2, m3));

    float hm  = heat[h * WW + w];
    float val = hm * sqrtf(m);
    float av  = fabsf(hm);

    // block reduce (256 threads = 8 warps)
    unsigned mask = 0xFFFFFFFFu;
    #pragma unroll
    for (int off = 16; off > 0; off >>= 1) {
        val += __shfl_down_sync(mask, val, off);
        av  += __shfl_down_sync(mask, av,  off);
    }
    __shared__ float sv[8], sa[8];
    int lane = threadIdx.x & 31, wid = threadIdx.x >> 5;
    if (lane == 0) { sv[wid] = val; sa[wid] = av; }
    __syncthreads();
    if (wid == 0) {
        float v = (lane < 8) ? sv[lane] : 0.0f;
        float a = (lane < 8) ? sa[lane] : 0.0f;
        #pragma unroll
        for (int off = 4; off > 0; off >>= 1) {
            v += __shfl_down_sync(mask, v, off);
            a += __shfl_down_sync(mask, a, off);
        }
        if (lane == 0) {
            atomicAdd(&g_term1,  v);
            atomicAdd(&g_sumabs, a);
        }
    }
}

// ---------------------------------------------------------------------------
// K3: term2 — per-point sum over pixels of (hm*dist + (1-hm)*maxd)^-5.
// Lanes own points (PT=4 each, 128 slots), warp shares a 128-pixel chunk of
// one row: hm load is warp-uniform; dy^2 precomputed per thread; fw walks the
// row. 65536 threads total.
// ---------------------------------------------------------------------------
#define PT 4
#define CHUNKPIX 128

__global__ void term2_kernel(const float* __restrict__ heat,
                             const float* __restrict__ pts) {
    int tid   = blockIdx.x * blockDim.x + threadIdx.x;
    int slot  = tid & 127;   // point group: points [slot*4, slot*4+4)
    int chunk = tid >> 7;    // 0..511 : half-row of pixels
    int h      = chunk >> 1;
    int wstart = (chunk & 1) << 7;

    float maxd = g_maxd;
    float fh = (float)h;

    float px[PT], dy2[PT], acc[PT];
    #pragma unroll
    for (int k = 0; k < PT; k++) {
        int p = slot * PT + k;
        float py  = __ldg(&pts[2 * p + 0]);
        float pxx = __ldg(&pts[2 * p + 1]);
        float dy = fh - py;
        px[k] = pxx; dy2[k] = dy * dy; acc[k] = 0.0f;
    }

    const float* hrow = heat + h * WW + wstart;
    float fw = (float)wstart;
    #pragma unroll 4
    for (int j = 0; j < CHUNKPIX; j++) {
        float hm   = __ldg(&hrow[j]);
        float cpix = fmaf(-hm, maxd, maxd);   // (1-hm)*maxd
        #pragma unroll
        for (int k = 0; k < PT; k++) {
            float dx   = fw - px[k];
            float d2   = fmaf(dx, dx, dy2[k]);
            float dist = fsqrt_approx(d2);
            float wd   = fmaf(hm, dist, cpix);
            float r    = frcp_approx(wd);
            float r2   = r * r;
            float r4   = r2 * r2;
            acc[k] = fmaf(r4, r, acc[k]);     // += wd^-5
        }
        fw += 1.0f;
    }

    #pragma unroll
    for (int k = 0; k < PT; k++)
        atomicAdd(&g_sums[slot * PT + k], acc[k]);
}

// ---------------------------------------------------------------------------
// K4: finalize — soft_min_p = (mean_pix wd^-5)^(-1/5); out = term1/sumabs +
// mean_p soft_min.
// ---------------------------------------------------------------------------
__global__ void final_kernel(float* __restrict__ out) {
    int p = threadIdx.x;  // 512
    float m = g_sums[p] * (1.0f / (float)NPIX);
    float soft = powf(m, -0.2f);

    __shared__ float sm[PP];
    sm[p] = soft;
    __syncthreads();
    for (int s = PP / 2; s > 0; s >>= 1) {
        if (p < s) sm[p] += sm[p + s];
        __syncthreads();
    }
    if (p == 0) {
        out[0] = g_term1 / g_sumabs + sm[0] * (1.0f / (float)PP);
    }
}

// ---------------------------------------------------------------------------
extern "C" void kernel_launch(void* const* d_in, const int* in_sizes, int n_in,
                              void* d_out, int out_size) {
    const float* heat = (const float*)d_in[0];   // (256,256) float32
    const float* pts  = (const float*)d_in[1];   // (512,2)   float32
    float* out = (float*)d_out;

    prep_kernel<<<1, PP>>>(pts);
    term1_kernel<<<HH, WW>>>(heat, pts);
    term2_kernel<<<256, 256>>>(heat, pts);
    final_kernel<<<1, PP>>>(out);
}

// round 2
// speedup vs baseline: 1.2818x; 1.2818x over previous
#include <cuda_runtime.h>

typedef unsigned long long ull;

#define HH 256
#define WW 256
#define PP 512
#define NPIX (HH * WW)
#define NB_T2 256
#define NB_T1 256
#define NBLK (NB_T2 + NB_T1)

// Scratch (device globals — zero-initialized at load; every run re-zeroes them
// in the finalize step, so each graph replay starts clean).
__device__ float g_sums[PP];     // per-point sum of wd^-5 over all pixels
__device__ float g_term1;        // sum hm * min_dist
__device__ float g_sumabs;       // sum |hm|
__device__ unsigned g_count;     // block completion counter

// ---- packed f32x2 helpers (FFMA2 path: only reachable via PTX) ----
__device__ __forceinline__ ull pack2(float lo, float hi) {
    ull r; asm("mov.b64 %0, {%1, %2};" : "=l"(r) : "f"(lo), "f"(hi)); return r;
}
__device__ __forceinline__ void unpack2(ull v, float& lo, float& hi) {
    asm("mov.b64 {%0, %1}, %2;" : "=f"(lo), "=f"(hi) : "l"(v));
}
__device__ __forceinline__ ull add2(ull a, ull b) {
    ull d; asm("add.rn.f32x2 %0, %1, %2;" : "=l"(d) : "l"(a), "l"(b)); return d;
}
__device__ __forceinline__ ull mul2(ull a, ull b) {
    ull d; asm("mul.rn.f32x2 %0, %1, %2;" : "=l"(d) : "l"(a), "l"(b)); return d;
}
__device__ __forceinline__ ull fma2(ull a, ull b, ull c) {
    ull d; asm("fma.rn.f32x2 %0, %1, %2, %3;" : "=l"(d) : "l"(a), "l"(b), "l"(c)); return d;
}
__device__ __forceinline__ float fsqrt_approx(float x) {
    float y; asm("sqrt.approx.f32 %0, %1;" : "=f"(y) : "f"(x)); return y;
}
__device__ __forceinline__ float frcp_approx(float x) {
    float y; asm("rcp.approx.f32 %0, %1;" : "=f"(y) : "f"(x)); return y;
}

// ---------------------------------------------------------------------------
// Single fused kernel.
//   blocks [0, 256):   term2 — block b handles pixel row b, all 512 points
//                      (2 points per thread, packed f32x2 math)
//   blocks [256, 512): term1 — block handles row b-256, per-pixel min over P
//   last block to finish: finalize + re-zero globals (self-cleaning replays)
// ---------------------------------------------------------------------------
__global__ void __launch_bounds__(256, 4)
whd_fused(const float* __restrict__ heat,
          const float* __restrict__ pts,
          float* __restrict__ out) {
    __shared__ __align__(16) unsigned char sraw[4096];
    __shared__ float swred[16];
    __shared__ float s_scal;
    __shared__ int s_last;

    const int t = threadIdx.x;
    const int b = blockIdx.x;
    const int lane = t & 31;
    const int wid = t >> 5;
    const unsigned FULL = 0xFFFFFFFFu;

    if (b < NB_T2) {
        // ================= term2: row = b =================
        const int row = b;
        // points 2t, 2t+1 (coalesced float4: py0,px0,py1,px1)
        float4 pv = ((const float4*)pts)[t];

        // --- block-local maxd: max lattice distance = corner distance ---
        const float C = 255.0f;
        float mdy0 = fmaxf(pv.x, fabsf(C - pv.x));
        float mdx0 = fmaxf(pv.y, fabsf(C - pv.y));
        float mdy1 = fmaxf(pv.z, fabsf(C - pv.z));
        float mdx1 = fmaxf(pv.w, fabsf(C - pv.w));
        float m2 = fmaxf(fmaf(mdy0, mdy0, mdx0 * mdx0),
                         fmaf(mdy1, mdy1, mdx1 * mdx1));
        #pragma unroll
        for (int off = 16; off > 0; off >>= 1)
            m2 = fmaxf(m2, __shfl_xor_sync(FULL, m2, off));
        if (lane == 0) swred[wid] = m2;
        __syncthreads();
        if (t == 0) {
            float mm = swred[0];
            #pragma unroll
            for (int i = 1; i < 8; i++) mm = fmaxf(mm, swred[i]);
            s_scal = sqrtf(mm);
        }
        __syncthreads();
        const float maxd = s_scal;

        // --- stage row: pre-duplicated packed (hm,hm) and (cpix,cpix) ---
        ull* hmp_s = (ull*)sraw;         // 256 * 8B = 2KB
        ull* cpp_s = hmp_s + 256;        // 2KB
        {
            float hm = heat[row * WW + t];
            float cp = fmaf(-hm, maxd, maxd);   // (1-hm)*maxd
            hmp_s[t] = pack2(hm, hm);
            cpp_s[t] = pack2(cp, cp);
        }
        __syncthreads();

        // --- packed inner loop over the row ---
        const float fh = (float)row;
        float dy0 = fh - pv.x, dy1 = fh - pv.z;
        ull dy2p = pack2(dy0 * dy0, dy1 * dy1);
        ull npxp = pack2(-pv.y, -pv.w);
        ull accp = pack2(0.0f, 0.0f);
        ull fwp  = pack2(0.0f, 0.0f);
        const ull onep = pack2(1.0f, 1.0f);

        #pragma unroll 4
        for (int j = 0; j < WW; j++) {
            ull hmp = hmp_s[j];                 // LDS.64 (broadcast)
            ull cpp = cpp_s[j];                 // LDS.64
            ull dxp = add2(fwp, npxp);          // fw - px
            ull d2p = fma2(dxp, dxp, dy2p);     // dx^2 + dy^2
            float d2a, d2b; unpack2(d2p, d2a, d2b);
            float da = fsqrt_approx(d2a);       // MUFU
            float db = fsqrt_approx(d2b);       // MUFU
            ull dp  = pack2(da, db);
            ull wdp = fma2(hmp, dp, cpp);       // hm*dist + (1-hm)*maxd
            float wa, wb; unpack2(wdp, wa, wb);
            float ra = frcp_approx(wa);         // MUFU
            float rb = frcp_approx(wb);         // MUFU
            ull rp = pack2(ra, rb);
            ull r2 = mul2(rp, rp);
            ull r4 = mul2(r2, r2);
            accp = fma2(r4, rp, accp);          // += wd^-5
            fwp = add2(fwp, onep);
        }
        float a0, a1; unpack2(accp, a0, a1);
        atomicAdd(&g_sums[2 * t + 0], a0);
        atomicAdd(&g_sums[2 * t + 1], a1);
    } else {
        // ================= term1: row = b - NB_T2 =================
        const int row = b - NB_T2;
        float2* pc = (float2*)sraw;              // 512 * 8B = 4KB
        const float fh = (float)row;
        for (int p = t; p < PP; p += 256) {
            float py = pts[2 * p + 0];
            float px = pts[2 * p + 1];
            float dy = fh - py;
            pc[p] = make_float2(px, dy * dy);
        }
        __syncthreads();

        const float fw = (float)t;
        float m0 = 3.4e38f, m1 = 3.4e38f, m2v = 3.4e38f, m3 = 3.4e38f;
        #pragma unroll 4
        for (int p = 0; p < PP; p += 4) {
            float2 a0 = pc[p + 0], a1 = pc[p + 1], a2 = pc[p + 2], a3 = pc[p + 3];
            float t0 = fw - a0.x; m0  = fminf(m0,  fmaf(t0, t0, a0.y));
            float t1 = fw - a1.x; m1  = fminf(m1,  fmaf(t1, t1, a1.y));
            float t2 = fw - a2.x; m2v = fminf(m2v, fmaf(t2, t2, a2.y));
            float t3 = fw - a3.x; m3  = fminf(m3,  fmaf(t3, t3, a3.y));
        }
        float m = fminf(fminf(m0, m1), fminf(m2v, m3));

        float hm  = heat[row * WW + t];
        float val = hm * sqrtf(m);
        float av  = fabsf(hm);
        #pragma unroll
        for (int off = 16; off > 0; off >>= 1) {
            val += __shfl_down_sync(FULL, val, off);
            av  += __shfl_down_sync(FULL, av,  off);
        }
        if (lane == 0) { swred[wid] = val; swred[8 + wid] = av; }
        __syncthreads();
        if (wid == 0) {
            float v = (lane < 8) ? swred[lane] : 0.0f;
            float a = (lane < 8) ? swred[8 + lane] : 0.0f;
            #pragma unroll
            for (int off = 4; off > 0; off >>= 1) {
                v += __shfl_down_sync(FULL, v, off);
                a += __shfl_down_sync(FULL, a, off);
            }
            if (lane == 0) {
                atomicAdd(&g_term1,  v);
                atomicAdd(&g_sumabs, a);
            }
        }
    }

    // ================= last-block finalize =================
    __threadfence();             // make this thread's RED atomics visible
    __syncthreads();
    if (t == 0)
        s_last = (atomicAdd(&g_count, 1u) == (unsigned)(NBLK - 1));
    __syncthreads();

    if (s_last) {
        // soft_min_p = (mean wd^-5)^(-1/5); reduce mean over points
        float local = 0.0f;
        #pragma unroll
        for (int k = 0; k < 2; k++) {
            int p = t + k * 256;
            float s = __ldcg(&g_sums[p]);
            g_sums[p] = 0.0f;                       // re-zero for next replay
            float mv = s * (1.0f / (float)NPIX);
            local += exp2f(-0.2f * __log2f(mv));    // mv^(-0.2)
        }
        #pragma unroll
        for (int off = 16; off > 0; off >>= 1)
            local += __shfl_down_sync(FULL, local, off);
        if (lane == 0) swred[wid] = local;
        __syncthreads();
        if (t == 0) {
            float tot = 0.0f;
            #pragma unroll
            for (int i = 0; i < 8; i++) tot += swred[i];
            float t1 = __ldcg(&g_term1);
            float sa = __ldcg(&g_sumabs);
            out[0] = t1 / sa + tot * (1.0f / (float)PP);
            g_term1  = 0.0f;                        // self-clean for replay
            g_sumabs = 0.0f;
            g_count  = 0u;
        }
    }
}

// ---------------------------------------------------------------------------
extern "C" void kernel_launch(void* const* d_in, const int* in_sizes, int n_in,
                              void* d_out, int out_size) {
    const float* heat = (const float*)d_in[0];   // (256,256) float32
    const float* pts  = (const float*)d_in[1];   // (512,2)   float32
    float* out = (float*)d_out;

    whd_fused<<<NBLK, 256>>>(heat, pts, out);
}

// round 4
// speedup vs baseline: 1.5891x; 1.2398x over previous
#include <cuda_runtime.h>

typedef unsigned long long ull;

#define HH 256
#define WW 256
#define PP 512
#define NPIX (HH * WW)
#define NB_T2 512          // term2: half-row blocks (2 per row)
#define NB_T1 256          // term1: one block per row
#define NBLK (NB_T2 + NB_T1)
#define HALFW 128

// Scratch (device globals — zero-initialized at load; finalize re-zeroes them
// so every graph replay starts clean).
__device__ float g_sums[PP];
__device__ float g_term1;
__device__ float g_sumabs;
__device__ unsigned g_count;

// ---- packed f32x2 helpers ----
__device__ __forceinline__ ull pack2(float lo, float hi) {
    ull r; asm("mov.b64 %0, {%1, %2};" : "=l"(r) : "f"(lo), "f"(hi)); return r;
}
__device__ __forceinline__ void unpack2(ull v, float& lo, float& hi) {
    asm("mov.b64 {%0, %1}, %2;" : "=f"(lo), "=f"(hi) : "l"(v));
}
__device__ __forceinline__ ull add2(ull a, ull b) {
    ull d; asm("add.rn.f32x2 %0, %1, %2;" : "=l"(d) : "l"(a), "l"(b)); return d;
}
__device__ __forceinline__ ull mul2(ull a, ull b) {
    ull d; asm("mul.rn.f32x2 %0, %1, %2;" : "=l"(d) : "l"(a), "l"(b)); return d;
}
__device__ __forceinline__ ull fma2(ull a, ull b, ull c) {
    ull d; asm("fma.rn.f32x2 %0, %1, %2, %3;" : "=l"(d) : "l"(a), "l"(b), "l"(c)); return d;
}
__device__ __forceinline__ float fsqrt_approx(float x) {
    float y; asm("sqrt.approx.f32 %0, %1;" : "=f"(y) : "f"(x)); return y;
}
__device__ __forceinline__ float frcp_approx(float x) {
    float y; asm("rcp.approx.f32 %0, %1;" : "=f"(y) : "f"(x)); return y;
}

// ---------------------------------------------------------------------------
// One fused kernel, 768 blocks:
//   [0, 512):   term2 — block b: row b>>1, pixel half [b&1]*128, all 512
//               points (2/thread, packed f32x2)
//   [512, 768): term1 — row b-512, per-pixel min over P
//   last block: finalize + re-zero (self-cleaning for graph replays)
// ---------------------------------------------------------------------------
__global__ void __launch_bounds__(256)
whd_fused(const float* __restrict__ heat,
          const float* __restrict__ pts,
          float* __restrict__ out) {
    __shared__ __align__(16) unsigned char sraw[4096];
    __shared__ float swred[16];
    __shared__ float s_scal;
    __shared__ int s_last;

    const int t = threadIdx.x;
    const int b = blockIdx.x;
    const int lane = t & 31;
    const int wid = t >> 5;
    const unsigned FULL = 0xFFFFFFFFu;

    if (b < NB_T2) {
        // ================= term2: row = b>>1, half = b&1 =================
        const int row = b >> 1;
        const int wstart = (b & 1) << 7;
        float4 pv = ((const float4*)pts)[t];   // points 2t, 2t+1

        // block maxd: max lattice distance = max corner distance (exact)
        const float C = 255.0f;
        float mdy0 = fmaxf(pv.x, fabsf(C - pv.x));
        float mdx0 = fmaxf(pv.y, fabsf(C - pv.y));
        float mdy1 = fmaxf(pv.z, fabsf(C - pv.z));
        float mdx1 = fmaxf(pv.w, fabsf(C - pv.w));
        float m2 = fmaxf(fmaf(mdy0, mdy0, mdx0 * mdx0),
                         fmaf(mdy1, mdy1, mdx1 * mdx1));
        #pragma unroll
        for (int off = 16; off > 0; off >>= 1)
            m2 = fmaxf(m2, __shfl_xor_sync(FULL, m2, off));
        if (lane == 0) swred[wid] = m2;
        __syncthreads();
        if (t == 0) {
            float mm = swred[0];
            #pragma unroll
            for (int i = 1; i < 8; i++) mm = fmaxf(mm, swred[i]);
            s_scal = sqrtf(mm);
        }
        __syncthreads();
        const float maxd = s_scal;

        // stage half-row: packed (hm,hm), (cpix,cpix)
        ull* hmp_s = (ull*)sraw;          // 128 * 8B
        ull* cpp_s = hmp_s + HALFW;       // 128 * 8B
        if (t < HALFW) {
            float hm = heat[row * WW + wstart + t];
            float cp = fmaf(-hm, maxd, maxd);
            hmp_s[t] = pack2(hm, hm);
            cpp_s[t] = pack2(cp, cp);
        }
        __syncthreads();

        const float fh = (float)row;
        float dy0 = fh - pv.x, dy1 = fh - pv.z;
        ull dy2p = pack2(dy0 * dy0, dy1 * dy1);
        ull npxp = pack2(-pv.y, -pv.w);
        ull accp = pack2(0.0f, 0.0f);
        ull fwp  = pack2((float)wstart, (float)wstart);
        const ull onep = pack2(1.0f, 1.0f);

        #pragma unroll 8
        for (int j = 0; j < HALFW; j++) {
            ull hmp = hmp_s[j];
            ull cpp = cpp_s[j];
            ull dxp = add2(fwp, npxp);
            ull d2p = fma2(dxp, dxp, dy2p);
            float d2a, d2b; unpack2(d2p, d2a, d2b);
            float da = fsqrt_approx(d2a);
            float db = fsqrt_approx(d2b);
            ull dp  = pack2(da, db);
            ull wdp = fma2(hmp, dp, cpp);
            float wa, wb; unpack2(wdp, wa, wb);
            float ra = frcp_approx(wa);
            float rb = frcp_approx(wb);
            ull rp = pack2(ra, rb);
            ull r2 = mul2(rp, rp);
            ull r4 = mul2(r2, r2);
            accp = fma2(r4, rp, accp);
            fwp = add2(fwp, onep);
        }
        float a0, a1; unpack2(accp, a0, a1);
        atomicAdd(&g_sums[2 * t + 0], a0);
        atomicAdd(&g_sums[2 * t + 1], a1);
    } else {
        // ================= term1: row = b - NB_T2 =================
        const int row = b - NB_T2;
        float2* pc = (float2*)sraw;       // 512 * 8B
        const float fh = (float)row;
        for (int p = t; p < PP; p += 256) {
            float py = pts[2 * p + 0];
            float px = pts[2 * p + 1];
            float dy = fh - py;
            pc[p] = make_float2(px, dy * dy);
        }
        __syncthreads();

        const float fw = (float)t;
        float m0 = 3.4e38f, m1 = 3.4e38f, m2v = 3.4e38f, m3 = 3.4e38f;
        #pragma unroll 4
        for (int p = 0; p < PP; p += 4) {
            float2 a0 = pc[p + 0], a1 = pc[p + 1], a2 = pc[p + 2], a3 = pc[p + 3];
            float t0 = fw - a0.x; m0  = fminf(m0,  fmaf(t0, t0, a0.y));
            float t1 = fw - a1.x; m1  = fminf(m1,  fmaf(t1, t1, a1.y));
            float t2 = fw - a2.x; m2v = fminf(m2v, fmaf(t2, t2, a2.y));
            float t3 = fw - a3.x; m3  = fminf(m3,  fmaf(t3, t3, a3.y));
        }
        float m = fminf(fminf(m0, m1), fminf(m2v, m3));

        float hm  = heat[row * WW + t];
        float val = hm * sqrtf(m);
        float av  = fabsf(hm);
        #pragma unroll
        for (int off = 16; off > 0; off >>= 1) {
            val += __shfl_down_sync(FULL, val, off);
            av  += __shfl_down_sync(FULL, av,  off);
        }
        if (lane == 0) { swred[wid] = val; swred[8 + wid] = av; }
        __syncthreads();
        if (wid == 0) {
            float v = (lane < 8) ? swred[lane] : 0.0f;
            float a = (lane < 8) ? swred[8 + lane] : 0.0f;
            #pragma unroll
            for (int off = 4; off > 0; off >>= 1) {
                v += __shfl_down_sync(FULL, v, off);
                a += __shfl_down_sync(FULL, a, off);
            }
            if (lane == 0) {
                atomicAdd(&g_term1,  v);
                atomicAdd(&g_sumabs, a);
            }
        }
    }

    // ================= last-block finalize =================
    __threadfence();
    __syncthreads();
    if (t == 0)
        s_last = (atomicAdd(&g_count, 1u) == (unsigned)(NBLK - 1));
    __syncthreads();

    if (s_last) {
        float local = 0.0f;
        #pragma unroll
        for (int k = 0; k < 2; k++) {
            int p = t + k * 256;
            float s = __ldcg(&g_sums[p]);
            g_sums[p] = 0.0f;
            float mv = s * (1.0f / (float)NPIX);
            local += exp2f(-0.2f * __log2f(mv));   // mv^(-0.2)
        }
        #pragma unroll
        for (int off = 16; off > 0; off >>= 1)
            local += __shfl_down_sync(FULL, local, off);
        if (lane == 0) swred[wid] = local;
        __syncthreads();
        if (t == 0) {
            float tot = 0.0f;
            #pragma unroll
            for (int i = 0; i < 8; i++) tot += swred[i];
            float t1 = __ldcg(&g_term1);
            float sa = __ldcg(&g_sumabs);
            out[0] = t1 / sa + tot * (1.0f / (float)PP);
            g_term1  = 0.0f;
            g_sumabs = 0.0f;
            g_count  = 0u;
        }
    }
}

// ---------------------------------------------------------------------------
extern "C" void kernel_launch(void* const* d_in, const int* in_sizes, int n_in,
                              void* d_out, int out_size) {
    const float* heat = (const float*)d_in[0];
    const float* pts  = (const float*)d_in[1];
    float* out = (float*)d_out;

    whd_fused<<<NBLK, 256>>>(heat, pts, out);
}

// round 6
// speedup vs baseline: 1.7007x; 1.0702x over previous
#include <cuda_runtime.h>

typedef unsigned long long ull;

#define HH 256
#define WW 256
#define PP 512
#define NPIX (HH * WW)
#define NB_T2 512          // term2: half-row blocks (2 per row)
#define NB_T1 256          // term1: one block per row
#define NBLK (NB_T2 + NB_T1)
#define HALFW 128

// Scratch (device globals — zero-initialized at load; finalize re-zeroes them
// so every graph replay starts clean).
__device__ float g_sums[PP];
__device__ float g_term1;
__device__ float g_sumabs;
__device__ unsigned g_count;

// ---- packed f32x2 helpers ----
__device__ __forceinline__ ull pack2(float lo, float hi) {
    ull r; asm("mov.b64 %0, {%1, %2};" : "=l"(r) : "f"(lo), "f"(hi)); return r;
}
__device__ __forceinline__ void unpack2(ull v, float& lo, float& hi) {
    asm("mov.b64 {%0, %1}, %2;" : "=f"(lo), "=f"(hi) : "l"(v));
}
__device__ __forceinline__ ull add2(ull a, ull b) {
    ull d; asm("add.rn.f32x2 %0, %1, %2;" : "=l"(d) : "l"(a), "l"(b)); return d;
}
__device__ __forceinline__ ull mul2(ull a, ull b) {
    ull d; asm("mul.rn.f32x2 %0, %1, %2;" : "=l"(d) : "l"(a), "l"(b)); return d;
}
__device__ __forceinline__ ull fma2(ull a, ull b, ull c) {
    ull d; asm("fma.rn.f32x2 %0, %1, %2, %3;" : "=l"(d) : "l"(a), "l"(b), "l"(c)); return d;
}
__device__ __forceinline__ float fsqrt_approx(float x) {
    float y; asm("sqrt.approx.f32 %0, %1;" : "=f"(y) : "f"(x)); return y;
}
__device__ __forceinline__ float frcp_approx(float x) {
    float y; asm("rcp.approx.f32 %0, %1;" : "=f"(y) : "f"(x)); return y;
}

// ---------------------------------------------------------------------------
// One fused kernel, 768 blocks:
//   [0, 512):   term2 — block b: row b>>1, pixel half [b&1]*128, all 512
//               points (2/thread, packed d2, paired-rcp soft-min accumulate)
//   [512, 768): term1 — row b-512, per-pixel min over P
//   last block: finalize + re-zero (self-cleaning for graph replays)
// ---------------------------------------------------------------------------
__global__ void __launch_bounds__(256, 6)
whd_fused(const float* __restrict__ heat,
          const float* __restrict__ pts,
          float* __restrict__ out) {
    __shared__ __align__(16) unsigned char sraw[4096];
    __shared__ float swred[16];
    __shared__ float s_scal;
    __shared__ int s_last;

    const int t = threadIdx.x;
    const int b = blockIdx.x;
    const int lane = t & 31;
    const int wid = t >> 5;
    const unsigned FULL = 0xFFFFFFFFu;

    if (b < NB_T2) {
        // ================= term2: row = b>>1, half = b&1 =================
        const int row = b >> 1;
        const int wstart = (b & 1) << 7;
        float4 pv = ((const float4*)pts)[t];   // points 2t, 2t+1

        // block maxd: max lattice distance = max corner distance (exact)
        const float C = 255.0f;
        float mdy0 = fmaxf(pv.x, fabsf(C - pv.x));
        float mdx0 = fmaxf(pv.y, fabsf(C - pv.y));
        float mdy1 = fmaxf(pv.z, fabsf(C - pv.z));
        float mdx1 = fmaxf(pv.w, fabsf(C - pv.w));
        float m2 = fmaxf(fmaf(mdy0, mdy0, mdx0 * mdx0),
                         fmaf(mdy1, mdy1, mdx1 * mdx1));
        #pragma unroll
        for (int off = 16; off > 0; off >>= 1)
            m2 = fmaxf(m2, __shfl_xor_sync(FULL, m2, off));
        if (lane == 0) swred[wid] = m2;
        __syncthreads();
        if (t == 0) {
            float mm = swred[0];
            #pragma unroll
            for (int i = 1; i < 8; i++) mm = fmaxf(mm, swred[i]);
            s_scal = sqrtf(mm);
        }
        __syncthreads();
        const float maxd = s_scal;

        // stage half-row interleaved: (hm, cpix) -> single LDS.64 per iter
        float2* shc = (float2*)sraw;      // 128 * 8B
        if (t < HALFW) {
            float hm = heat[row * WW + wstart + t];
            shc[t] = make_float2(hm, fmaf(-hm, maxd, maxd));  // (hm, (1-hm)*maxd)
        }
        __syncthreads();

        const float fh = (float)row;
        float dy0 = fh - pv.x, dy1 = fh - pv.z;
        ull dy2p = pack2(dy0 * dy0, dy1 * dy1);
        ull npxp = pack2(-pv.y, -pv.w);
        ull accp = pack2(0.0f, 0.0f);
        ull fwp  = pack2((float)wstart, (float)wstart);
        const ull onep = pack2(1.0f, 1.0f);

        #pragma unroll 8
        for (int j = 0; j < HALFW; j++) {
            float2 hc = shc[j];                 // LDS.64 broadcast (hm, cpix)
            ull dxp = add2(fwp, npxp);          // fw - px (packed)
            ull d2p = fma2(dxp, dxp, dy2p);     // dx^2 + dy^2
            float d2a, d2b; unpack2(d2p, d2a, d2b);
            float sa = fsqrt_approx(d2a);       // MUFU
            float sb = fsqrt_approx(d2b);       // MUFU
            float wa = fmaf(hc.x, sa, hc.y);    // hm*dist + cpix
            float wb = fmaf(hc.x, sb, hc.y);
            float pm = wa * wb;                 // paired reciprocal:
            float ip = frcp_approx(pm);         //   1 MUFU for both points
            float ra = ip * wb;
            float rb = ip * wa;
            ull rp = pack2(ra, rb);
            ull r2 = mul2(rp, rp);
            ull r4 = mul2(r2, r2);
            accp = fma2(r4, rp, accp);          // += wd^-5
            fwp = add2(fwp, onep);
        }
        float a0, a1; unpack2(accp, a0, a1);
        atomicAdd(&g_sums[2 * t + 0], a0);
        atomicAdd(&g_sums[2 * t + 1], a1);
    } else {
        // ================= term1: row = b - NB_T2 =================
        const int row = b - NB_T2;
        float2* pc = (float2*)sraw;       // 512 * 8B
        const float fh = (float)row;
        for (int p = t; p < PP; p += 256) {
            float py = pts[2 * p + 0];
            float px = pts[2 * p + 1];
            float dy = fh - py;
            pc[p] = make_float2(px, dy * dy);
        }
        __syncthreads();

        const float fw = (float)t;
        float m0 = 3.4e38f, m1 = 3.4e38f, m2v = 3.4e38f, m3 = 3.4e38f;
        #pragma unroll 4
        for (int p = 0; p < PP; p += 4) {
            float2 a0 = pc[p + 0], a1 = pc[p + 1], a2 = pc[p + 2], a3 = pc[p + 3];
            float t0 = fw - a0.x; m0  = fminf(m0,  fmaf(t0, t0, a0.y));
            float t1 = fw - a1.x; m1  = fminf(m1,  fmaf(t1, t1, a1.y));
            float t2 = fw - a2.x; m2v = fminf(m2v, fmaf(t2, t2, a2.y));
            float t3 = fw - a3.x; m3  = fminf(m3,  fmaf(t3, t3, a3.y));
        }
        float m = fminf(fminf(m0, m1), fminf(m2v, m3));

        float hm  = heat[row * WW + t];
        float val = hm * sqrtf(m);
        float av  = fabsf(hm);
        #pragma unroll
        for (int off = 16; off > 0; off >>= 1) {
            val += __shfl_down_sync(FULL, val, off);
            av  += __shfl_down_sync(FULL, av,  off);
        }
        if (lane == 0) { swred[wid] = val; swred[8 + wid] = av; }
        __syncthreads();
        if (wid == 0) {
            float v = (lane < 8) ? swred[lane] : 0.0f;
            float a = (lane < 8) ? swred[8 + lane] : 0.0f;
            #pragma unroll
            for (int off = 4; off > 0; off >>= 1) {
                v += __shfl_down_sync(FULL, v, off);
                a += __shfl_down_sync(FULL, a, off);
            }
            if (lane == 0) {
                atomicAdd(&g_term1,  v);
                atomicAdd(&g_sumabs, a);
            }
        }
    }

    // ================= last-block finalize =================
    __threadfence();
    __syncthreads();
    if (t == 0)
        s_last = (atomicAdd(&g_count, 1u) == (unsigned)(NBLK - 1));
    __syncthreads();

    if (s_last) {
        float local = 0.0f;
        #pragma unroll
        for (int k = 0; k < 2; k++) {
            int p = t + k * 256;
            float s = __ldcg(&g_sums[p]);
            g_sums[p] = 0.0f;
            float mv = s * (1.0f / (float)NPIX);
            local += exp2f(-0.2f * __log2f(mv));   // mv^(-0.2)
        }
        #pragma unroll
        for (int off = 16; off > 0; off >>= 1)
            local += __shfl_down_sync(FULL, local, off);
        if (lane == 0) swred[wid] = local;
        __syncthreads();
        if (t == 0) {
            float tot = 0.0f;
            #pragma unroll
            for (int i = 0; i < 8; i++) tot += swred[i];
            float t1 = __ldcg(&g_term1);
            float sa = __ldcg(&g_sumabs);
            out[0] = t1 / sa + tot * (1.0f / (float)PP);
            g_term1  = 0.0f;
            g_sumabs = 0.0f;
            g_count  = 0u;
        }
    }
}

// ---------------------------------------------------------------------------
extern "C" void kernel_launch(void* const* d_in, const int* in_sizes, int n_in,
                              void* d_out, int out_size) {
    const float* heat = (const float*)d_in[0];
    const float* pts  = (const float*)d_in[1];
    float* out = (float*)d_out;

    whd_fused<<<NBLK, 256>>>(heat, pts, out);
}

// round 7
// speedup vs baseline: 1.8777x; 1.1041x over previous
#include <cuda_runtime.h>

typedef unsigned long long ull;

#define HH 256
#define WW 256
#define PP 512
#define NPIX (HH * WW)
#define NB_T1 256          // term1: one block per row (long blocks, go first)
#define NB_T2 1024         // term2: quarter-row blocks (4 per row)
#define NBLK (NB_T1 + NB_T2)
#define QW 64              // pixels per term2 block

// Scratch (device globals — zero-initialized at load; finalize re-zeroes them
// so every graph replay starts clean).
__device__ float g_sums4[4][PP];   // per-quarter partial sums of wd^-5
__device__ float g_term1;
__device__ float g_sumabs;
__device__ unsigned g_count;

// ---- packed f32x2 helpers ----
__device__ __forceinline__ ull pack2(float lo, float hi) {
    ull r; asm("mov.b64 %0, {%1, %2};" : "=l"(r) : "f"(lo), "f"(hi)); return r;
}
__device__ __forceinline__ void unpack2(ull v, float& lo, float& hi) {
    asm("mov.b64 {%0, %1}, %2;" : "=f"(lo), "=f"(hi) : "l"(v));
}
__device__ __forceinline__ ull add2(ull a, ull b) {
    ull d; asm("add.rn.f32x2 %0, %1, %2;" : "=l"(d) : "l"(a), "l"(b)); return d;
}
__device__ __forceinline__ ull mul2(ull a, ull b) {
    ull d; asm("mul.rn.f32x2 %0, %1, %2;" : "=l"(d) : "l"(a), "l"(b)); return d;
}
__device__ __forceinline__ ull fma2(ull a, ull b, ull c) {
    ull d; asm("fma.rn.f32x2 %0, %1, %2, %3;" : "=l"(d) : "l"(a), "l"(b), "l"(c)); return d;
}
__device__ __forceinline__ float fsqrt_approx(float x) {
    float y; asm("sqrt.approx.f32 %0, %1;" : "=f"(y) : "f"(x)); return y;
}
__device__ __forceinline__ float frcp_approx(float x) {
    float y; asm("rcp.approx.f32 %0, %1;" : "=f"(y) : "f"(x)); return y;
}

// ---------------------------------------------------------------------------
// One fused kernel, 1280 blocks:
//   [0, 256):     term1 — row b, per-pixel min over P (longest blocks first)
//   [256, 1280):  term2 — unit u=b-256: row u>>2, pixel quarter (u&3)*64,
//                 all 512 points (2/thread, packed math, paired rcp)
//   last block:   finalize + re-zero (self-cleaning for graph replays)
// ---------------------------------------------------------------------------
__global__ void __launch_bounds__(256, 6)
whd_fused(const float* __restrict__ heat,
          const float* __restrict__ pts,
          float* __restrict__ out) {
    __shared__ __align__(16) unsigned char sraw[4096];
    __shared__ float swred[16];
    __shared__ float s_scal;
    __shared__ int s_last;

    const int t = threadIdx.x;
    const int b = blockIdx.x;
    const int lane = t & 31;
    const int wid = t >> 5;
    const unsigned FULL = 0xFFFFFFFFu;

    if (b >= NB_T1) {
        // ================= term2: quarter-row =================
        const int u = b - NB_T1;
        const int row = u >> 2;
        const int qi = u & 3;
        const int wstart = qi << 6;
        float4 pv = ((const float4*)pts)[t];   // points 2t, 2t+1

        // block maxd: max lattice distance = max corner distance (exact)
        const float C = 255.0f;
        float mdy0 = fmaxf(pv.x, fabsf(C - pv.x));
        float mdx0 = fmaxf(pv.y, fabsf(C - pv.y));
        float mdy1 = fmaxf(pv.z, fabsf(C - pv.z));
        float mdx1 = fmaxf(pv.w, fabsf(C - pv.w));
        float m2 = fmaxf(fmaf(mdy0, mdy0, mdx0 * mdx0),
                         fmaf(mdy1, mdy1, mdx1 * mdx1));
        #pragma unroll
        for (int off = 16; off > 0; off >>= 1)
            m2 = fmaxf(m2, __shfl_xor_sync(FULL, m2, off));
        if (lane == 0) swred[wid] = m2;
        __syncthreads();
        if (t == 0) {
            float mm = swred[0];
            #pragma unroll
            for (int i = 1; i < 8; i++) mm = fmaxf(mm, swred[i]);
            s_scal = sqrtf(mm);
        }
        __syncthreads();
        const float maxd = s_scal;

        // stage quarter-row interleaved (hm, cpix): one LDS.64 per iter
        float2* shc = (float2*)sraw;      // 64 * 8B
        if (t < QW) {
            float hm = heat[row * WW + wstart + t];
            shc[t] = make_float2(hm, fmaf(-hm, maxd, maxd));  // (hm, (1-hm)*maxd)
        }
        __syncthreads();

        const float fh = (float)row;
        float dy0 = fh - pv.x, dy1 = fh - pv.z;
        ull dy2p = pack2(dy0 * dy0, dy1 * dy1);
        ull dxp  = pack2((float)wstart - pv.y, (float)wstart - pv.w);
        ull accp = pack2(0.0f, 0.0f);
        const ull onep = pack2(1.0f, 1.0f);

        #pragma unroll 8
        for (int j = 0; j < QW; j++) {
            float2 hc = shc[j];                 // LDS.64 broadcast (hm, cpix)
            ull d2p = fma2(dxp, dxp, dy2p);     // dx^2 + dy^2 (packed)
            float d2a, d2b; unpack2(d2p, d2a, d2b);
            float sa = fsqrt_approx(d2a);       // MUFU
            float sb = fsqrt_approx(d2b);       // MUFU
            float wa = fmaf(hc.x, sa, hc.y);    // hm*dist + cpix
            float wb = fmaf(hc.x, sb, hc.y);
            float pm = wa * wb;                 // paired reciprocal:
            float ip = frcp_approx(pm);         //   1 MUFU for both points
            float ra = ip * wb;
            float rb = ip * wa;
            ull rp = pack2(ra, rb);
            ull r2 = mul2(rp, rp);
            ull r4 = mul2(r2, r2);
            accp = fma2(r4, rp, accp);          // += wd^-5
            dxp = add2(dxp, onep);              // dx advances by 1
        }
        float a0, a1; unpack2(accp, a0, a1);
        atomicAdd(&g_sums4[qi][2 * t + 0], a0);
        atomicAdd(&g_sums4[qi][2 * t + 1], a1);
    } else {
        // ================= term1: row = b =================
        const int row = b;
        float2* pc = (float2*)sraw;       // 512 * 8B
        const float fh = (float)row;
        for (int p = t; p < PP; p += 256) {
            float py = pts[2 * p + 0];
            float px = pts[2 * p + 1];
            float dy = fh - py;
            pc[p] = make_float2(px, dy * dy);
        }
        __syncthreads();

        const float fw = (float)t;
        float m0 = 3.4e38f, m1 = 3.4e38f, m2v = 3.4e38f, m3 = 3.4e38f;
        #pragma unroll 4
        for (int p = 0; p < PP; p += 4) {
            float2 a0 = pc[p + 0], a1 = pc[p + 1], a2 = pc[p + 2], a3 = pc[p + 3];
            float t0 = fw - a0.x; m0  = fminf(m0,  fmaf(t0, t0, a0.y));
            float t1 = fw - a1.x; m1  = fminf(m1,  fmaf(t1, t1, a1.y));
            float t2 = fw - a2.x; m2v = fminf(m2v, fmaf(t2, t2, a2.y));
            float t3 = fw - a3.x; m3  = fminf(m3,  fmaf(t3, t3, a3.y));
        }
        float m = fminf(fminf(m0, m1), fminf(m2v, m3));

        float hm  = heat[row * WW + t];
        float val = hm * sqrtf(m);
        float av  = fabsf(hm);
        #pragma unroll
        for (int off = 16; off > 0; off >>= 1) {
            val += __shfl_down_sync(FULL, val, off);
            av  += __shfl_down_sync(FULL, av,  off);
        }
        if (lane == 0) { swred[wid] = val; swred[8 + wid] = av; }
        __syncthreads();
        if (wid == 0) {
            float v = (lane < 8) ? swred[lane] : 0.0f;
            float a = (lane < 8) ? swred[8 + lane] : 0.0f;
            #pragma unroll
            for (int off = 4; off > 0; off >>= 1) {
                v += __shfl_down_sync(FULL, v, off);
                a += __shfl_down_sync(FULL, a, off);
            }
            if (lane == 0) {
                atomicAdd(&g_term1,  v);
                atomicAdd(&g_sumabs, a);
            }
        }
    }

    // ================= last-block finalize =================
    __threadfence();
    __syncthreads();
    if (t == 0)
        s_last = (atomicAdd(&g_count, 1u) == (unsigned)(NBLK - 1));
    __syncthreads();

    if (s_last) {
        float local = 0.0f;
        #pragma unroll
        for (int k = 0; k < 2; k++) {
            int p = t + k * 256;
            float s = __ldcg(&g_sums4[0][p]) + __ldcg(&g_sums4[1][p])
                    + __ldcg(&g_sums4[2][p]) + __ldcg(&g_sums4[3][p]);
            g_sums4[0][p] = 0.0f; g_sums4[1][p] = 0.0f;
            g_sums4[2][p] = 0.0f; g_sums4[3][p] = 0.0f;
            float mv = s * (1.0f / (float)NPIX);
            local += exp2f(-0.2f * __log2f(mv));   // mv^(-0.2)
        }
        #pragma unroll
        for (int off = 16; off > 0; off >>= 1)
            local += __shfl_down_sync(FULL, local, off);
        if (lane == 0) swred[wid] = local;
        __syncthreads();
        if (t == 0) {
            float tot = 0.0f;
            #pragma unroll
            for (int i = 0; i < 8; i++) tot += swred[i];
            float t1 = __ldcg(&g_term1);
            float sa = __ldcg(&g_sumabs);
            out[0] = t1 / sa + tot * (1.0f / (float)PP);
            g_term1  = 0.0f;
            g_sumabs = 0.0f;
            g_count  = 0u;
        }
    }
}

// ---------------------------------------------------------------------------
extern "C" void kernel_launch(void* const* d_in, const int* in_sizes, int n_in,
                              void* d_out, int out_size) {
    const float* heat = (const float*)d_in[0];
    const float* pts  = (const float*)d_in[1];
    float* out = (float*)d_out;

    whd_fused<<<NBLK, 256>>>(heat, pts, out);
}

// round 10
// speedup vs baseline: 1.9608x; 1.0442x over previous
#include <cuda_runtime.h>

typedef unsigned long long ull;

#define HH 256
#define WW 256
#define PP 512
#define NPIX (HH * WW)
#define NB_T1 256          // term1: one block per row (long blocks, go first)
#define NB_T2 2048         // term2: eighth-row blocks (8 per row)
#define NBLK (NB_T1 + NB_T2)
#define QW 32              // pixels per term2 block

// Scratch (device globals — zero-initialized at load; finalize re-zeroes them
// so every graph replay starts clean).
__device__ float g_sums8[8][PP];   // per-eighth partial sums of wd^-5
__device__ float g_term1;
__device__ float g_sumabs;
__device__ unsigned g_count;

// ---- packed f32x2 helpers ----
__device__ __forceinline__ ull pack2(float lo, float hi) {
    ull r; asm("mov.b64 %0, {%1, %2};" : "=l"(r) : "f"(lo), "f"(hi)); return r;
}
__device__ __forceinline__ void unpack2(ull v, float& lo, float& hi) {
    asm("mov.b64 {%0, %1}, %2;" : "=f"(lo), "=f"(hi) : "l"(v));
}
__device__ __forceinline__ ull add2(ull a, ull b) {
    ull d; asm("add.rn.f32x2 %0, %1, %2;" : "=l"(d) : "l"(a), "l"(b)); return d;
}
__device__ __forceinline__ ull mul2(ull a, ull b) {
    ull d; asm("mul.rn.f32x2 %0, %1, %2;" : "=l"(d) : "l"(a), "l"(b)); return d;
}
__device__ __forceinline__ ull fma2(ull a, ull b, ull c) {
    ull d; asm("fma.rn.f32x2 %0, %1, %2, %3;" : "=l"(d) : "l"(a), "l"(b), "l"(c)); return d;
}
__device__ __forceinline__ float fsqrt_approx(float x) {
    float y; asm("sqrt.approx.f32 %0, %1;" : "=f"(y) : "f"(x)); return y;
}
__device__ __forceinline__ float frcp_approx(float x) {
    float y; asm("rcp.approx.f32 %0, %1;" : "=f"(y) : "f"(x)); return y;
}

// ---------------------------------------------------------------------------
// One fused kernel, 2304 blocks:
//   [0, 256):     term1 — row b, per-pixel min over P (long blocks first)
//   [256, 2304):  term2 — unit u=b-256: row u>>3, pixel eighth (u&7)*32,
//                 512 points (2/thread); 2 pixels/iter, 4-way paired rcp
//   last block:   finalize + re-zero (self-cleaning for graph replays)
// ---------------------------------------------------------------------------
__global__ void __launch_bounds__(256, 6)
whd_fused(const float* __restrict__ heat,
          const float* __restrict__ pts,
          float* __restrict__ out) {
    __shared__ __align__(16) unsigned char sraw[4096];
    __shared__ float swred[16];
    __shared__ float s_scal;
    __shared__ int s_last;

    const int t = threadIdx.x;
    const int b = blockIdx.x;
    const int lane = t & 31;
    const int wid = t >> 5;
    const unsigned FULL = 0xFFFFFFFFu;

    if (b >= NB_T1) {
        // ================= term2: eighth-row =================
        const int u = b - NB_T1;
        const int row = u >> 3;
        const int qi = u & 7;
        const int wstart = qi << 5;
        float4 pv = ((const float4*)pts)[t];   // points 2t, 2t+1

        // block maxd: max lattice distance = max corner distance (exact)
        const float C = 255.0f;
        float mdy0 = fmaxf(pv.x, fabsf(C - pv.x));
        float mdx0 = fmaxf(pv.y, fabsf(C - pv.y));
        float mdy1 = fmaxf(pv.z, fabsf(C - pv.z));
        float mdx1 = fmaxf(pv.w, fabsf(C - pv.w));
        float m2 = fmaxf(fmaf(mdy0, mdy0, mdx0 * mdx0),
                         fmaf(mdy1, mdy1, mdx1 * mdx1));
        #pragma unroll
        for (int off = 16; off > 0; off >>= 1)
            m2 = fmaxf(m2, __shfl_xor_sync(FULL, m2, off));
        if (lane == 0) swred[wid] = m2;
        __syncthreads();
        if (t == 0) {
            float mm = swred[0];
            #pragma unroll
            for (int i = 1; i < 8; i++) mm = fmaxf(mm, swred[i]);
            s_scal = sqrtf(mm);
        }
        __syncthreads();
        const float maxd = s_scal;

        // stage 32 pixels interleaved (hm, cpix); read back as float4 pairs
        float2* shc2 = (float2*)sraw;     // 32 * 8B
        if (t < QW) {
            float hm = heat[row * WW + wstart + t];
            shc2[t] = make_float2(hm, fmaf(-hm, maxd, maxd));
        }
        __syncthreads();
        const float4* shc4 = (const float4*)sraw;  // [16]: (hm0,cp0,hm1,cp1)

        const float fh = (float)row;
        float dy0 = fh - pv.x, dy1 = fh - pv.z;
        ull dy2p = pack2(dy0 * dy0, dy1 * dy1);
        ull dxp  = pack2((float)wstart - pv.y, (float)wstart - pv.w);
        ull accp = pack2(0.0f, 0.0f);
        const ull onep = pack2(1.0f, 1.0f);

        #pragma unroll 4
        for (int k = 0; k < QW / 2; k++) {
            float4 hc = shc4[k];                // LDS.128: 2 pixels (hm,cp)
            // pixel 0 distances (packed over 2 points)
            ull d2p0 = fma2(dxp, dxp, dy2p);
            dxp = add2(dxp, onep);
            // pixel 1 distances
            ull d2p1 = fma2(dxp, dxp, dy2p);
            dxp = add2(dxp, onep);
            float d2a0, d2b0, d2a1, d2b1;
            unpack2(d2p0, d2a0, d2b0);
            unpack2(d2p1, d2a1, d2b1);
            float sa0 = fsqrt_approx(d2a0);     // 4 independent MUFU sqrt
            float sb0 = fsqrt_approx(d2b0);
            float sa1 = fsqrt_approx(d2a1);
            float sb1 = fsqrt_approx(d2b1);
            float wa0 = fmaf(hc.x, sa0, hc.y);  // wd = hm*dist + cpix
            float wb0 = fmaf(hc.x, sb0, hc.y);
            float wa1 = fmaf(hc.z, sa1, hc.w);
            float wb1 = fmaf(hc.z, sb1, hc.w);
            // 4-way paired reciprocal: 1 MUFU rcp for all four wd values
            float p0   = wa0 * wb0;
            float p1   = wa1 * wb1;
            float pall = p0 * p1;
            float ip   = frcp_approx(pall);
            float q0   = ip * p1;               // 1/(wa0*wb0)
            float q1   = ip * p0;               // 1/(wa1*wb1)
            float ra0 = q0 * wb0, rb0 = q0 * wa0;
            float ra1 = q1 * wb1, rb1 = q1 * wa1;
            // wd^-5 accumulate, packed per pixel
            ull rp0 = pack2(ra0, rb0);
            ull rp1 = pack2(ra1, rb1);
            ull r20 = mul2(rp0, rp0);
            ull r21 = mul2(rp1, rp1);
            ull r40 = mul2(r20, r20);
            ull r41 = mul2(r21, r21);
            accp = fma2(r40, rp0, accp);
            accp = fma2(r41, rp1, accp);
        }
        float a0, a1; unpack2(accp, a0, a1);
        atomicAdd(&g_sums8[qi][2 * t + 0], a0);
        atomicAdd(&g_sums8[qi][2 * t + 1], a1);
    } else {
        // ================= term1: row = b =================
        const int row = b;
        float2* pc = (float2*)sraw;       // 512 * 8B
        const float fh = (float)row;
        for (int p = t; p < PP; p += 256) {
            float py = pts[2 * p + 0];
            float px = pts[2 * p + 1];
            float dy = fh - py;
            pc[p] = make_float2(px, dy * dy);
        }
        __syncthreads();

        const float fw = (float)t;
        float m0 = 3.4e38f, m1 = 3.4e38f, m2v = 3.4e38f, m3 = 3.4e38f;
        #pragma unroll 4
        for (int p = 0; p < PP; p += 4) {
            float2 a0 = pc[p + 0], a1 = pc[p + 1], a2 = pc[p + 2], a3 = pc[p + 3];
            float t0 = fw - a0.x; m0  = fminf(m0,  fmaf(t0, t0, a0.y));
            float t1 = fw - a1.x; m1  = fminf(m1,  fmaf(t1, t1, a1.y));
            float t2 = fw - a2.x; m2v = fminf(m2v, fmaf(t2, t2, a2.y));
            float t3 = fw - a3.x; m3  = fminf(m3,  fmaf(t3, t3, a3.y));
        }
        float m = fminf(fminf(m0, m1), fminf(m2v, m3));

        float hm  = heat[row * WW + t];
        float val = hm * sqrtf(m);
        float av  = fabsf(hm);
        #pragma unroll
        for (int off = 16; off > 0; off >>= 1) {
            val += __shfl_down_sync(FULL, val, off);
            av  += __shfl_down_sync(FULL, av,  off);
        }
        if (lane == 0) { swred[wid] = val; swred[8 + wid] = av; }
        __syncthreads();
        if (wid == 0) {
            float v = (lane < 8) ? swred[lane] : 0.0f;
            float a = (lane < 8) ? swred[8 + lane] : 0.0f;
            #pragma unroll
            for (int off = 4; off > 0; off >>= 1) {
                v += __shfl_down_sync(FULL, v, off);
                a += __shfl_down_sync(FULL, a, off);
            }
            if (lane == 0) {
                atomicAdd(&g_term1,  v);
                atomicAdd(&g_sumabs, a);
            }
        }
    }

    // ================= last-block finalize =================
    __threadfence();
    __syncthreads();
    if (t == 0)
        s_last = (atomicAdd(&g_count, 1u) == (unsigned)(NBLK - 1));
    __syncthreads();

    if (s_last) {
        float local = 0.0f;
        #pragma unroll
        for (int k = 0; k < 2; k++) {
            int p = t + k * 256;
            float s = 0.0f;
            #pragma unroll
            for (int q = 0; q < 8; q++) {
                s += __ldcg(&g_sums8[q][p]);
                g_sums8[q][p] = 0.0f;
            }
            float mv = s * (1.0f / (float)NPIX);
            local += exp2f(-0.2f * __log2f(mv));   // mv^(-0.2)
        }
        #pragma unroll
        for (int off = 16; off > 0; off >>= 1)
            local += __shfl_down_sync(FULL, local, off);
        if (lane == 0) swred[wid] = local;
        __syncthreads();
        if (t == 0) {
            float tot = 0.0f;
            #pragma unroll
            for (int i = 0; i < 8; i++) tot += swred[i];
            float t1 = __ldcg(&g_term1);
            float sa = __ldcg(&g_sumabs);
            out[0] = t1 / sa + tot * (1.0f / (float)PP);
            g_term1  = 0.0f;
            g_sumabs = 0.0f;
            g_count  = 0u;
        }
    }
}

// ---------------------------------------------------------------------------
extern "C" void kernel_launch(void* const* d_in, const int* in_sizes, int n_in,
                              void* d_out, int out_size) {
    const float* heat = (const float*)d_in[0];
    const float* pts  = (const float*)d_in[1];
    float* out = (float*)d_out;

    whd_fused<<<NBLK, 256>>>(heat, pts, out);
}

// round 13
// speedup vs baseline: 1.9783x; 1.0089x over previous
#include <cuda_runtime.h>

typedef unsigned long long ull;

#define HH 256
#define WW 256
#define PP 512
#define NPIX (HH * WW)
#define NB_T1 256          // term1: one block per row (long blocks, go first)
#define NB_T2 2048         // term2: eighth-row blocks (8 per row)
#define NBLK (NB_T1 + NB_T2)
#define QW 32              // pixels per term2 block

// Scratch (device globals — zero-initialized at load; finalize re-zeroes them
// so every graph replay starts clean).
__device__ float g_sums8[8][PP];   // per-eighth partial sums of wd^-5
__device__ float g_term1;
__device__ float g_sumabs;
__device__ unsigned g_count;

// ---- packed f32x2 helpers ----
__device__ __forceinline__ ull pack2(float lo, float hi) {
    ull r; asm("mov.b64 %0, {%1, %2};" : "=l"(r) : "f"(lo), "f"(hi)); return r;
}
__device__ __forceinline__ void unpack2(ull v, float& lo, float& hi) {
    asm("mov.b64 {%0, %1}, %2;" : "=f"(lo), "=f"(hi) : "l"(v));
}
__device__ __forceinline__ ull add2(ull a, ull b) {
    ull d; asm("add.rn.f32x2 %0, %1, %2;" : "=l"(d) : "l"(a), "l"(b)); return d;
}
__device__ __forceinline__ ull mul2(ull a, ull b) {
    ull d; asm("mul.rn.f32x2 %0, %1, %2;" : "=l"(d) : "l"(a), "l"(b)); return d;
}
__device__ __forceinline__ ull fma2(ull a, ull b, ull c) {
    ull d; asm("fma.rn.f32x2 %0, %1, %2, %3;" : "=l"(d) : "l"(a), "l"(b), "l"(c)); return d;
}
__device__ __forceinline__ float fsqrt_approx(float x) {
    float y; asm("sqrt.approx.f32 %0, %1;" : "=f"(y) : "f"(x)); return y;
}
__device__ __forceinline__ float frcp_approx(float x) {
    float y; asm("rcp.approx.f32 %0, %1;" : "=f"(y) : "f"(x)); return y;
}

// ---------------------------------------------------------------------------
// One fused kernel, 2304 blocks:
//   [0, 256):     term1 — row b, per-pixel min over P (long blocks first)
//   [256, 2304):  term2 — unit u=b-256: row u>>3, pixel eighth (u&7)*32,
//                 512 points (2/thread); 2 pixels/iter, 4-way paired rcp,
//                 fully unrolled 16-iteration loop
//   last block:   finalize + re-zero (self-cleaning for graph replays)
// ---------------------------------------------------------------------------
__global__ void __launch_bounds__(256, 7)
whd_fused(const float* __restrict__ heat,
          const float* __restrict__ pts,
          float* __restrict__ out) {
    __shared__ __align__(16) unsigned char sraw[4096];
    __shared__ float swred[16];
    __shared__ float s_scal;
    __shared__ int s_last;

    const int t = threadIdx.x;
    const int b = blockIdx.x;
    const int lane = t & 31;
    const int wid = t >> 5;
    const unsigned FULL = 0xFFFFFFFFu;

    if (b >= NB_T1) {
        // ================= term2: eighth-row =================
        const int u = b - NB_T1;
        const int row = u >> 3;
        const int qi = u & 7;
        const int wstart = qi << 5;
        float4 pv = ((const float4*)pts)[t];   // points 2t, 2t+1

        // block maxd: max lattice distance = max corner distance (exact)
        const float C = 255.0f;
        float mdy0 = fmaxf(pv.x, fabsf(C - pv.x));
        float mdx0 = fmaxf(pv.y, fabsf(C - pv.y));
        float mdy1 = fmaxf(pv.z, fabsf(C - pv.z));
        float mdx1 = fmaxf(pv.w, fabsf(C - pv.w));
        float m2 = fmaxf(fmaf(mdy0, mdy0, mdx0 * mdx0),
                         fmaf(mdy1, mdy1, mdx1 * mdx1));
        #pragma unroll
        for (int off = 16; off > 0; off >>= 1)
            m2 = fmaxf(m2, __shfl_xor_sync(FULL, m2, off));
        if (lane == 0) swred[wid] = m2;
        __syncthreads();
        if (t == 0) {
            float mm = swred[0];
            #pragma unroll
            for (int i = 1; i < 8; i++) mm = fmaxf(mm, swred[i]);
            s_scal = sqrtf(mm);
        }
        __syncthreads();
        const float maxd = s_scal;

        // stage 32 pixels interleaved (hm, cpix); read back as float4 pairs
        float2* shc2 = (float2*)sraw;     // 32 * 8B
        if (t < QW) {
            float hm = heat[row * WW + wstart + t];
            shc2[t] = make_float2(hm, fmaf(-hm, maxd, maxd));
        }
        __syncthreads();
        const float4* shc4 = (const float4*)sraw;  // [16]: (hm0,cp0,hm1,cp1)

        const float fh = (float)row;
        float dy0 = fh - pv.x, dy1 = fh - pv.z;
        ull dy2p = pack2(dy0 * dy0, dy1 * dy1);
        ull dxp  = pack2((float)wstart - pv.y, (float)wstart - pv.w);
        ull accp = pack2(0.0f, 0.0f);
        const ull onep = pack2(1.0f, 1.0f);

        #pragma unroll
        for (int k = 0; k < QW / 2; k++) {
            float4 hc = shc4[k];                // LDS.128: 2 pixels (hm,cp)
            // pixel 0 distances (packed over 2 points)
            ull d2p0 = fma2(dxp, dxp, dy2p);
            dxp = add2(dxp, onep);
            // pixel 1 distances
            ull d2p1 = fma2(dxp, dxp, dy2p);
            dxp = add2(dxp, onep);
            float d2a0, d2b0, d2a1, d2b1;
            unpack2(d2p0, d2a0, d2b0);
            unpack2(d2p1, d2a1, d2b1);
            float sa0 = fsqrt_approx(d2a0);     // 4 independent MUFU sqrt
            float sb0 = fsqrt_approx(d2b0);
            float sa1 = fsqrt_approx(d2a1);
            float sb1 = fsqrt_approx(d2b1);
            float wa0 = fmaf(hc.x, sa0, hc.y);  // wd = hm*dist + cpix
            float wb0 = fmaf(hc.x, sb0, hc.y);
            float wa1 = fmaf(hc.z, sa1, hc.w);
            float wb1 = fmaf(hc.z, sb1, hc.w);
            // 4-way paired reciprocal: 1 MUFU rcp for all four wd values
            float p0   = wa0 * wb0;
            float p1   = wa1 * wb1;
            float pall = p0 * p1;
            float ip   = frcp_approx(pall);
            float q0   = ip * p1;               // 1/(wa0*wb0)
            float q1   = ip * p0;               // 1/(wa1*wb1)
            float ra0 = q0 * wb0, rb0 = q0 * wa0;
            float ra1 = q1 * wb1, rb1 = q1 * wa1;
            // wd^-5 accumulate, packed per pixel
            ull rp0 = pack2(ra0, rb0);
            ull rp1 = pack2(ra1, rb1);
            ull r20 = mul2(rp0, rp0);
            ull r21 = mul2(rp1, rp1);
            ull r40 = mul2(r20, r20);
            ull r41 = mul2(r21, r21);
            accp = fma2(r40, rp0, accp);
            accp = fma2(r41, rp1, accp);
        }
        float a0, a1; unpack2(accp, a0, a1);
        atomicAdd(&g_sums8[qi][2 * t + 0], a0);
        atomicAdd(&g_sums8[qi][2 * t + 1], a1);
    } else {
        // ================= term1: row = b =================
        const int row = b;
        float4* pc4 = (float4*)sraw;      // 256 * 16B: (px0,dy2_0,px1,dy2_1)
        const float fh = (float)row;
        {
            float4 pw = ((const float4*)pts)[t];   // (py0,px0,py1,px1)
            float dy0 = fh - pw.x, dy1 = fh - pw.z;
            pc4[t] = make_float4(pw.y, dy0 * dy0, pw.w, dy1 * dy1);
        }
        __syncthreads();

        const float fw = (float)t;
        float m0 = 3.4e38f, m1 = 3.4e38f, m2v = 3.4e38f, m3 = 3.4e38f;
        #pragma unroll 8
        for (int i = 0; i < PP / 2; i += 2) {
            float4 v0 = pc4[i], v1 = pc4[i + 1];
            float t0 = fw - v0.x; m0  = fminf(m0,  fmaf(t0, t0, v0.y));
            float t1 = fw - v0.z; m1  = fminf(m1,  fmaf(t1, t1, v0.w));
            float t2 = fw - v1.x; m2v = fminf(m2v, fmaf(t2, t2, v1.y));
            float t3 = fw - v1.z; m3  = fminf(m3,  fmaf(t3, t3, v1.w));
        }
        float m = fminf(fminf(m0, m1), fminf(m2v, m3));

        float hm  = heat[row * WW + t];
        float val = hm * sqrtf(m);
        float av  = fabsf(hm);
        #pragma unroll
        for (int off = 16; off > 0; off >>= 1) {
            val += __shfl_down_sync(FULL, val, off);
            av  += __shfl_down_sync(FULL, av,  off);
        }
        if (lane == 0) { swred[wid] = val; swred[8 + wid] = av; }
        __syncthreads();
        if (wid == 0) {
            float v = (lane < 8) ? swred[lane] : 0.0f;
            float a = (lane < 8) ? swred[8 + lane] : 0.0f;
            #pragma unroll
            for (int off = 4; off > 0; off >>= 1) {
                v += __shfl_down_sync(FULL, v, off);
                a += __shfl_down_sync(FULL, a, off);
            }
            if (lane == 0) {
                atomicAdd(&g_term1,  v);
                atomicAdd(&g_sumabs, a);
            }
        }
    }

    // ================= last-block finalize =================
    __threadfence();
    __syncthreads();
    if (t == 0)
        s_last = (atomicAdd(&g_count, 1u) == (unsigned)(NBLK - 1));
    __syncthreads();

    if (s_last) {
        float local = 0.0f;
        #pragma unroll
        for (int k = 0; k < 2; k++) {
            int p = t + k * 256;
            float s = 0.0f;
            #pragma unroll
            for (int q = 0; q < 8; q++) {
                s += __ldcg(&g_sums8[q][p]);
                g_sums8[q][p] = 0.0f;
            }
            float mv = s * (1.0f / (float)NPIX);
            local += exp2f(-0.2f * __log2f(mv));   // mv^(-0.2)
        }
        #pragma unroll
        for (int off = 16; off > 0; off >>= 1)
            local += __shfl_down_sync(FULL, local, off);
        if (lane == 0) swred[wid] = local;
        __syncthreads();
        if (t == 0) {
            float tot = 0.0f;
            #pragma unroll
            for (int i = 0; i < 8; i++) tot += swred[i];
            float t1 = __ldcg(&g_term1);
            float sa = __ldcg(&g_sumabs);
            out[0] = t1 / sa + tot * (1.0f / (float)PP);
            g_term1  = 0.0f;
            g_sumabs = 0.0f;
            g_count  = 0u;
        }
    }
}

// ---------------------------------------------------------------------------
extern "C" void kernel_launch(void* const* d_in, const int* in_sizes, int n_in,
                              void* d_out, int out_size) {
    const float* heat = (const float*)d_in[0];
    const float* pts  = (const float*)d_in[1];
    float* out = (float*)d_out;

    whd_fused<<<NBLK, 256>>>(heat, pts, out);
}